// round 15
// baseline (speedup 1.0000x reference)
#include <cuda_runtime.h>
#include <cuda_fp16.h>
#include <cstdint>

// ---------------- scratch (device globals: allocation-free) ----------------
__device__ __half g_pool2h[512 * 9216];         // conv2 out, NCHW flat, fp16
__device__ __half g_fc1w_h[128 * 9216];         // fc1 weights, fp16
__device__ uint4  g_w2h[2304];                  // conv2 weights, pre-swizzled smem image
__device__ float  g_fc1out[512 * 128];          // fc1 accumulator (REDG target)

__device__ __forceinline__ uint32_t smem_u32(const void* p) {
    return (uint32_t)__cvta_generic_to_shared(p);
}
__device__ __forceinline__ uint64_t pack2(float lo, float hi) {
    uint64_t r;
    asm("mov.b64 %0, {%1, %2};" : "=l"(r) : "f"(lo), "f"(hi));
    return r;
}
__device__ __forceinline__ void fma2(uint64_t& d, uint64_t a, uint64_t b) {
    asm("fma.rn.f32x2 %0, %1, %2, %0;" : "+l"(d) : "l"(a), "l"(b));
}
__device__ __forceinline__ void unpack2(uint64_t v, float& lo, float& hi) {
    uint32_t l, h;
    asm("mov.b64 {%0, %1}, %2;" : "=r"(l), "=r"(h) : "l"(v));
    lo = __uint_as_float(l);
    hi = __uint_as_float(h);
}
__device__ __forceinline__ uint32_t cvt_f16x2(float hi, float lo) {
    uint32_t r;
    asm("cvt.rn.f16x2.f32 %0, %1, %2;" : "=r"(r) : "f"(hi), "f"(lo));
    return r;
}
__device__ __forceinline__ void cp16(uint32_t dst, const void* src) {
    asm volatile("cp.async.cg.shared.global [%0], [%1], 16;"
                 :: "r"(dst), "l"(src) : "memory");
}
__device__ __forceinline__ void redg_add(float* p, float v) {
    asm volatile("red.global.add.f32 [%0], %1;" :: "l"(p), "f"(v) : "memory");
}

// fp16 tensor-core MMA, fp32 accum (baseline PTX, sm_80+).
__device__ __forceinline__ void mma_f16(float c[4],
                                        uint32_t a0, uint32_t a1,
                                        uint32_t a2, uint32_t a3,
                                        uint32_t b0, uint32_t b1) {
    asm volatile(
        "mma.sync.aligned.m16n8k16.row.col.f32.f16.f16.f32 "
        "{%0,%1,%2,%3}, {%4,%5,%6,%7}, {%8,%9}, {%0,%1,%2,%3};"
        : "+f"(c[0]), "+f"(c[1]), "+f"(c[2]), "+f"(c[3])
        : "r"(a0), "r"(a1), "r"(a2), "r"(a3), "r"(b0), "r"(b1));
}
__device__ __forceinline__ void ldmx4(uint32_t r[4], uint32_t addr) {
    asm volatile(
        "ldmatrix.sync.aligned.m8n8.x4.shared.b16 {%0,%1,%2,%3}, [%4];"
        : "=r"(r[0]), "=r"(r[1]), "=r"(r[2]), "=r"(r[3]) : "r"(addr));
}

// ============================================================================
// K0: one-time weight conversions + zero the fc1 REDG accumulator.
// ============================================================================
__global__ void __launch_bounds__(512) cvt_weights(
    const float* __restrict__ w1fc,
    const float* __restrict__ w2conv)
{
    const int bid = blockIdx.x;
    if (bid < 128)
        g_fc1out[bid * 512 + threadIdx.x] = 0.0f;   // 128*512 = 65536 floats
    if (bid < 1152) {
        const int i = bid * 512 + threadIdx.x;
        const float2 v = *(const float2*)(w1fc + i * 2);
        *(uint32_t*)(g_fc1w_h + i * 2) = cvt_f16x2(v.y, v.x);
    } else {
        const int i = (bid - 1152) * 512 + threadIdx.x;   // 18432 total
        const int n = i / 288;
        const int r = i % 288;
        const int k = r / 9;
        const int s = r % 9;
        const int row = s * 64 + n;
        *(__half*)((char*)g_w2h + row * 64 +
            ((((k >> 3) ^ ((n >> 1) & 3)) << 4) | ((k & 7) << 1))) =
            __float2half_rn(w2conv[i]);
    }
}

// ============================================================================
// K1 (fused): conv1+relu+pool -> conv2 (fp16 m16n8k16) -> bias+relu+pool.
// (unchanged from round 13/14 — half-image, 2 CTAs/SM)
// ============================================================================
__global__ void __launch_bounds__(256, 2) convs_fused(
    const float* __restrict__ x,
    const float* __restrict__ w1,
    const float* __restrict__ b1,
    const float* __restrict__ b2)
{
    extern __shared__ char smc[];
    __half* s_a   = (__half*)smc;                 // 384 rows x 64B = 24576 B
    __half* s_b   = (__half*)(smc + 24576);       // 9*64 rows x 64B = 36864 B
    float*  s_img = (float*)(smc + 61440);        // 30*54 f32 = 6480 B
    __half* s_epi = (__half*)smc;                 // 288 pix x 66 (38016 B), reuse
    __shared__ uint64_t s_w1d[32 * 9];
    __shared__ float s_b1[32];
    __shared__ float s_bias[64];

    const int b    = blockIdx.x >> 1;
    const int half = blockIdx.x & 1;
    const int tid  = threadIdx.x;
    const int wid  = tid >> 5;
    const int lane = tid & 31;
    const int g    = lane >> 2;
    const int tig  = lane & 3;

    {
        const float4* src = (const float4*)(x + b * 2916 + half * 24 * 54);
        float4* dst = (float4*)s_img;
        for (int i = tid; i < 405; i += 256) dst[i] = src[i];
    }
    for (int i = tid; i < 32 * 9; i += 256) {
        const float wv = w1[i];
        s_w1d[i] = pack2(wv, wv);
    }
    if (tid < 32) s_b1[tid] = b1[tid];
    if (tid < 64) s_bias[tid] = b2[tid];
    {
        uint4* dst = (uint4*)s_b;
#pragma unroll
        for (int j = 0; j < 9; j++) dst[tid + j * 256] = g_w2h[tid + j * 256];
    }
    for (int i = 364 * 16 + tid; i < 384 * 16; i += 256)
        ((uint32_t*)s_a)[i] = 0u;
    __syncthreads();

    for (int m = tid; m < 364; m += 256) {
        const int r  = m / 26;
        const int pw = m % 26;
        float in[4][4];
#pragma unroll
        for (int rr = 0; rr < 4; rr++)
#pragma unroll
            for (int c = 0; c < 4; c++)
                in[rr][c] = s_img[(2 * r + rr) * 54 + 2 * pw + c];
        uint64_t ap[4][3];
#pragma unroll
        for (int rr = 0; rr < 4; rr++)
#pragma unroll
            for (int j = 0; j < 3; j++)
                ap[rr][j] = pack2(in[rr][j], in[rr][j + 1]);

        char* arow = (char*)s_a + m * 64;
        const int sw2 = (m >> 1) & 3;
#pragma unroll 2
        for (int oc2 = 0; oc2 < 16; oc2++) {
            const int oca = oc2 * 2, ocb = oca + 1;
            uint64_t va0 = 0ull, va1 = 0ull, vb0 = 0ull, vb1 = 0ull;
#pragma unroll
            for (int t = 0; t < 9; t++) {
                const uint64_t wa = s_w1d[oca * 9 + t];
                const uint64_t wb = s_w1d[ocb * 9 + t];
                fma2(va0, ap[t / 3][t % 3], wa);
                fma2(va1, ap[t / 3 + 1][t % 3], wa);
                fma2(vb0, ap[t / 3][t % 3], wb);
                fma2(vb1, ap[t / 3 + 1][t % 3], wb);
            }
            float a00, a01, a10, a11, b00, b01, b10, b11;
            unpack2(va0, a00, a01); unpack2(va1, a10, a11);
            unpack2(vb0, b00, b01); unpack2(vb1, b10, b11);
            float ma = fmaxf(fmaxf(a00, a01), fmaxf(a10, a11)) + s_b1[oca];
            float mb = fmaxf(fmaxf(b00, b01), fmaxf(b10, b11)) + s_b1[ocb];
            ma = fmaxf(ma, 0.0f);
            mb = fmaxf(mb, 0.0f);
            *(uint32_t*)(arow +
                ((((oca >> 3) ^ sw2) << 4) | ((oca & 7) << 1))) =
                cvt_f16x2(mb, ma);
        }
    }
    __syncthreads();

    float acc[3][8][4];
#pragma unroll
    for (int i = 0; i < 3; i++)
#pragma unroll
        for (int n = 0; n < 8; n++)
#pragma unroll
            for (int q = 0; q < 4; q++) acc[i][n][q] = 0.0f;

    const int mbase = wid * 48;

    const uint32_t a_base = smem_u32(s_a);
    const uint32_t b_base = smem_u32(s_b);
    const int lrow15 = lane & 15;
    const int lhi    = lane >> 4;
    const int bq     = (lane >> 3) & 1;
    const int bsw    = ((lane & 7) >> 1) & 3;
    const int brow_l = ((lane >> 4) & 1) * 8 + (lane & 7);

#pragma unroll 1
    for (int s = 0; s < 9; s++) {
        const int roff = (s / 3) * 26 + (s % 3);
        const int arow = mbase + roff + lrow15;
        const int asw  = (arow >> 1) & 3;
        const uint32_t a_row_addr = a_base + arow * 64;
        const uint32_t b_s_base   = b_base + (s * 64 + brow_l) * 64;

#pragma unroll
        for (int ks = 0; ks < 2; ks++) {
            const uint32_t aaddr =
                a_row_addr + ((uint32_t)((((ks << 1) + lhi) ^ asw)) << 4);
            const uint32_t bchunk =
                ((uint32_t)((((ks << 1) + bq) ^ bsw)) << 4);

            uint32_t bf[4][4];
#pragma unroll
            for (int p = 0; p < 4; p++)
                ldmx4(bf[p], b_s_base + p * 1024 + bchunk);

#pragma unroll
            for (int i = 0; i < 3; i++) {
                uint32_t a[4];
                ldmx4(a, aaddr + i * 1024);
#pragma unroll
                for (int nt = 0; nt < 8; nt++)
                    mma_f16(acc[i][nt], a[0], a[1], a[2], a[3],
                            bf[nt >> 1][(nt & 1) * 2],
                            bf[nt >> 1][(nt & 1) * 2 + 1]);
            }
        }
    }
    __syncthreads();

#pragma unroll
    for (int i = 0; i < 3; i++) {
        const int m0 = mbase + i * 16 + g;
        const int m1 = m0 + 8;
        const int r0 = m0 / 26, c0p = m0 % 26;
        const int r1 = m1 / 26, c1p = m1 % 26;
#pragma unroll
        for (int nt = 0; nt < 8; nt++) {
            const int col = nt * 8 + tig * 2;
            if (r0 < 12 && c0p < 24) {
                const int pix = r0 * 24 + c0p;
                *(uint32_t*)(s_epi + pix * 66 + col) =
                    cvt_f16x2(acc[i][nt][1] + s_bias[col + 1],
                              acc[i][nt][0] + s_bias[col]);
            }
            if (r1 < 12 && c1p < 24) {
                const int pix = r1 * 24 + c1p;
                *(uint32_t*)(s_epi + pix * 66 + col) =
                    cvt_f16x2(acc[i][nt][3] + s_bias[col + 1],
                              acc[i][nt][2] + s_bias[col]);
            }
        }
    }
    __syncthreads();

    __half* outp = g_pool2h + b * 9216 + half * 72;
    const __half2 z2 = __float2half2_rn(0.0f);
    for (int j = tid; j < 32 * 72; j += 256) {
        const int ocp = j / 72;
        const int p   = j % 72;
        const int pr  = p / 12, pw = p % 12;
        const __half* e = s_epi + ((2 * pr) * 24 + 2 * pw) * 66 + ocp * 2;
        const __half2 v00 = *(const __half2*)(e);
        const __half2 v01 = *(const __half2*)(e + 66);
        const __half2 v10 = *(const __half2*)(e + 24 * 66);
        const __half2 v11 = *(const __half2*)(e + 25 * 66);
        const __half2 mx =
            __hmax2(__hmax2(__hmax2(v00, v01), __hmax2(v10, v11)), z2);
        outp[(ocp * 2) * 144 + p]     = __low2half(mx);
        outp[(ocp * 2 + 1) * 144 + p] = __high2half(mx);
    }
}

// ============================================================================
// K2: fc1 split-K (16 ways) via fp16 m16n8k16 + cp.async 2-stage pipeline.
// Epilogue: red.global.add.f32 into g_fc1out (no partial round-trip).
// ============================================================================
__global__ void __launch_bounds__(256) fc1_tc()
{
    __shared__ __half sA[2][32 * 32];
    __shared__ __half sB[2][128 * 32];

    const int mt   = blockIdx.x;    // 0..15
    const int ks   = blockIdx.y;    // 0..15
    const int tid  = threadIdx.x;
    const int wid  = tid >> 5;
    const int lane = tid & 31;
    const int m0   = mt * 32;
    const int k0   = ks * 576;
    const int mi   = wid & 1;
    const int nq   = wid >> 1;      // 0..3

    uint32_t sa_off = 0;
    const __half* agp = nullptr;
    if (tid < 128) {
        const int m = tid >> 2, c = tid & 3;
        sa_off = m * 64 + ((c ^ ((m >> 1) & 3)) << 4);
        agp = g_pool2h + (m0 + m) * 9216 + k0 + c * 8;
    }
    uint32_t sb_off[2];
    const __half* bgp[2];
#pragma unroll
    for (int j = 0; j < 2; j++) {
        const int i = tid + j * 256;
        const int n = i >> 2, c = i & 3;
        sb_off[j] = n * 64 + ((c ^ ((n >> 1) & 3)) << 4);
        bgp[j] = g_fc1w_h + n * 9216 + k0 + c * 8;
    }

    const int lrow15 = lane & 15;
    const int lhi    = lane >> 4;
    const int bq     = (lane >> 3) & 1;
    const int bsw    = ((lane & 7) >> 1) & 3;
    const int brow_l = ((lane >> 4) & 1) * 8 + (lane & 7);

    const int arow = mi * 16 + lrow15;
    const int asw  = (arow >> 1) & 3;
    uint32_t aaddr_base[2], baddr_base[2];
#pragma unroll
    for (int buf = 0; buf < 2; buf++) {
        aaddr_base[buf] = smem_u32(sA[buf]) + arow * 64;
        baddr_base[buf] = smem_u32(sB[buf]) + (nq * 32 + brow_l) * 64;
    }

    float acc[4][4];
#pragma unroll
    for (int n = 0; n < 4; n++)
#pragma unroll
        for (int q = 0; q < 4; q++) acc[n][q] = 0.0f;

    auto issue = [&](int c, int buf) {
        const int koff = c * 32;
        if (tid < 128) cp16(smem_u32(sA[buf]) + sa_off, agp + koff);
        cp16(smem_u32(sB[buf]) + sb_off[0], bgp[0] + koff);
        cp16(smem_u32(sB[buf]) + sb_off[1], bgp[1] + koff);
        asm volatile("cp.async.commit_group;" ::: "memory");
    };

    issue(0, 0);

#pragma unroll 1
    for (int c = 0; c < 18; c++) {
        const int buf = c & 1;
        if (c + 1 < 18) {
            issue(c + 1, buf ^ 1);
            asm volatile("cp.async.wait_group 1;" ::: "memory");
        } else {
            asm volatile("cp.async.wait_group 0;" ::: "memory");
        }
        __syncthreads();

#pragma unroll
        for (int kstep = 0; kstep < 2; kstep++) {
            uint32_t a[4];
            ldmx4(a, aaddr_base[buf] +
                     ((uint32_t)((((kstep << 1) + lhi) ^ asw)) << 4));
            const uint32_t bchunk =
                ((uint32_t)((((kstep << 1) + bq) ^ bsw)) << 4);
            uint32_t bf[2][4];
#pragma unroll
            for (int p = 0; p < 2; p++)
                ldmx4(bf[p], baddr_base[buf] + p * 1024 + bchunk);
#pragma unroll
            for (int nt = 0; nt < 4; nt++)
                mma_f16(acc[nt], a[0], a[1], a[2], a[3],
                        bf[nt >> 1][(nt & 1) * 2],
                        bf[nt >> 1][(nt & 1) * 2 + 1]);
        }
        __syncthreads();
    }

    float* P = g_fc1out + m0 * 128;
    const int g   = lane >> 2;
    const int tig = lane & 3;
    const int r0  = mi * 16 + g;
#pragma unroll
    for (int n = 0; n < 4; n++) {
        const int c0 = nq * 32 + n * 8 + tig * 2;
        redg_add(P + r0 * 128 + c0,           acc[n][0]);
        redg_add(P + r0 * 128 + c0 + 1,       acc[n][1]);
        redg_add(P + (r0 + 8) * 128 + c0,     acc[n][2]);
        redg_add(P + (r0 + 8) * 128 + c0 + 1, acc[n][3]);
    }
}

// ============================================================================
// K3: bias + relu + fc2 (128->10).  g_fc1out is complete & L2-hot.
// ============================================================================
__global__ void __launch_bounds__(128) fc_tail(
    const float* __restrict__ b1,
    const float* __restrict__ w2,
    const float* __restrict__ b2,
    float* __restrict__ out)
{
    __shared__ float s_h[128];
    const int b   = blockIdx.x;
    const int tid = threadIdx.x;

    s_h[tid] = fmaxf(g_fc1out[b * 128 + tid] + b1[tid], 0.0f);
    __syncthreads();

    if (tid < 10) {
        float acc = b2[tid];
        const float* w = w2 + tid * 128;
#pragma unroll 8
        for (int k = 0; k < 128; k++)
            acc = fmaf(s_h[k], w[k], acc);
        out[b * 10 + tid] = acc;
    }
}

// ============================================================================
extern "C" void kernel_launch(void* const* d_in, const int* in_sizes, int n_in,
                              void* d_out, int out_size)
{
    const float* x   = (const float*)d_in[0];
    const float* c1w = (const float*)d_in[1];
    const float* c1b = (const float*)d_in[2];
    const float* c2w = (const float*)d_in[3];
    const float* c2b = (const float*)d_in[4];
    const float* f1w = (const float*)d_in[5];
    const float* f1b = (const float*)d_in[6];
    const float* f2w = (const float*)d_in[7];
    const float* f2b = (const float*)d_in[8];
    float* out       = (float*)d_out;

    const int smem = 24576 + 36864 + 6480;   // 67920 B
    cudaFuncSetAttribute(convs_fused,
                         cudaFuncAttributeMaxDynamicSharedMemorySize, smem);

    cvt_weights<<<1188, 512>>>(f1w, c2w);
    convs_fused<<<1024, 256, smem>>>(x, c1w, c1b, c2b);

    dim3 g2(16, 16);
    fc1_tc<<<g2, 256>>>();

    fc_tail<<<512, 128>>>(f1b, f2w, f2b, out);
}

// round 16
// speedup vs baseline: 1.0516x; 1.0516x over previous
#include <cuda_runtime.h>
#include <cuda_fp16.h>
#include <cstdint>

// ---------------- scratch (device globals: allocation-free) ----------------
__device__ __half g_pool2h[512 * 9216];         // conv2 out, NCHW flat, fp16
__device__ __half g_fc1w_h[128 * 9216];         // fc1 weights, fp16
__device__ uint4  g_w2h[2304];                  // conv2 weights, pre-swizzled smem image
__device__ float  g_fc1out[512 * 128];          // fc1 accumulator (REDG target)

__device__ __forceinline__ uint32_t smem_u32(const void* p) {
    return (uint32_t)__cvta_generic_to_shared(p);
}
__device__ __forceinline__ uint64_t pack2(float lo, float hi) {
    uint64_t r;
    asm("mov.b64 %0, {%1, %2};" : "=l"(r) : "f"(lo), "f"(hi));
    return r;
}
__device__ __forceinline__ void fma2(uint64_t& d, uint64_t a, uint64_t b) {
    asm("fma.rn.f32x2 %0, %1, %2, %0;" : "+l"(d) : "l"(a), "l"(b));
}
__device__ __forceinline__ void unpack2(uint64_t v, float& lo, float& hi) {
    uint32_t l, h;
    asm("mov.b64 {%0, %1}, %2;" : "=r"(l), "=r"(h) : "l"(v));
    lo = __uint_as_float(l);
    hi = __uint_as_float(h);
}
__device__ __forceinline__ uint32_t cvt_f16x2(float hi, float lo) {
    uint32_t r;
    asm("cvt.rn.f16x2.f32 %0, %1, %2;" : "=r"(r) : "f"(hi), "f"(lo));
    return r;
}
__device__ __forceinline__ void cp16(uint32_t dst, const void* src) {
    asm volatile("cp.async.cg.shared.global [%0], [%1], 16;"
                 :: "r"(dst), "l"(src) : "memory");
}
__device__ __forceinline__ void redg_add(float* p, float v) {
    asm volatile("red.global.add.f32 [%0], %1;" :: "l"(p), "f"(v) : "memory");
}

// fp16 tensor-core MMA, fp32 accum (baseline PTX, sm_80+).
__device__ __forceinline__ void mma_f16(float c[4],
                                        uint32_t a0, uint32_t a1,
                                        uint32_t a2, uint32_t a3,
                                        uint32_t b0, uint32_t b1) {
    asm volatile(
        "mma.sync.aligned.m16n8k16.row.col.f32.f16.f16.f32 "
        "{%0,%1,%2,%3}, {%4,%5,%6,%7}, {%8,%9}, {%0,%1,%2,%3};"
        : "+f"(c[0]), "+f"(c[1]), "+f"(c[2]), "+f"(c[3])
        : "r"(a0), "r"(a1), "r"(a2), "r"(a3), "r"(b0), "r"(b1));
}
__device__ __forceinline__ void ldmx4(uint32_t r[4], uint32_t addr) {
    asm volatile(
        "ldmatrix.sync.aligned.m8n8.x4.shared.b16 {%0,%1,%2,%3}, [%4];"
        : "=r"(r[0]), "=r"(r[1]), "=r"(r[2]), "=r"(r[3]) : "r"(addr));
}

// ============================================================================
// K0: one-time weight conversions + zero the fc1 REDG accumulator.
// ============================================================================
__global__ void __launch_bounds__(512) cvt_weights(
    const float* __restrict__ w1fc,
    const float* __restrict__ w2conv)
{
    const int bid = blockIdx.x;
    if (bid < 128)
        g_fc1out[bid * 512 + threadIdx.x] = 0.0f;   // 128*512 = 65536 floats
    if (bid < 1152) {
        const int i = bid * 512 + threadIdx.x;
        const float2 v = *(const float2*)(w1fc + i * 2);
        *(uint32_t*)(g_fc1w_h + i * 2) = cvt_f16x2(v.y, v.x);
    } else {
        const int i = (bid - 1152) * 512 + threadIdx.x;   // 18432 total
        const int n = i / 288;
        const int r = i % 288;
        const int k = r / 9;
        const int s = r % 9;
        const int row = s * 64 + n;
        *(__half*)((char*)g_w2h + row * 64 +
            ((((k >> 3) ^ ((n >> 1) & 3)) << 4) | ((k & 7) << 1))) =
            __float2half_rn(w2conv[i]);
    }
}

// ============================================================================
// K1 (fused): conv1+relu+pool -> conv2 (fp16 m16n8k16) -> bias+relu+pool.
// Half-image CTAs, 2/SM. NEW: weight staging via cp.async (group 1) hidden
// behind conv1; image in group 0 waited before conv1.
// ============================================================================
__global__ void __launch_bounds__(256, 2) convs_fused(
    const float* __restrict__ x,
    const float* __restrict__ w1,
    const float* __restrict__ b1,
    const float* __restrict__ b2)
{
    extern __shared__ char smc[];
    __half* s_a   = (__half*)smc;                 // 384 rows x 64B = 24576 B
    __half* s_b   = (__half*)(smc + 24576);       // 9*64 rows x 64B = 36864 B
    float*  s_img = (float*)(smc + 61440);        // 30*54 f32 = 6480 B
    __half* s_epi = (__half*)smc;                 // 288 pix x 66 (38016 B), reuse
    __shared__ uint64_t s_w1d[32 * 9];
    __shared__ float s_b1[32];
    __shared__ float s_bias[64];

    const int b    = blockIdx.x >> 1;
    const int half = blockIdx.x & 1;
    const int tid  = threadIdx.x;
    const int wid  = tid >> 5;
    const int lane = tid & 31;
    const int g    = lane >> 2;
    const int tig  = lane & 3;

    // ---- phase 0: async image (group 0) + async weights (group 1) ----
    {
        const char* src = (const char*)(x + b * 2916 + half * 24 * 54);
        const uint32_t dimg = smem_u32(s_img);
        for (int i = tid; i < 405; i += 256)          // 30x54 f32 = 405 x 16B
            cp16(dimg + i * 16, src + i * 16);
        asm volatile("cp.async.commit_group;" ::: "memory");

        const uint32_t dw = smem_u32(s_b);
#pragma unroll
        for (int j = 0; j < 9; j++)
            cp16(dw + (tid + j * 256) * 16, g_w2h + tid + j * 256);
        asm volatile("cp.async.commit_group;" ::: "memory");
    }
    // small sync-path loads + A zero-pad while copies fly
    for (int i = tid; i < 32 * 9; i += 256) {
        const float wv = w1[i];
        s_w1d[i] = pack2(wv, wv);
    }
    if (tid < 32) s_b1[tid] = b1[tid];
    if (tid < 64) s_bias[tid] = b2[tid];
    for (int i = 364 * 16 + tid; i < 384 * 16; i += 256)
        ((uint32_t*)s_a)[i] = 0u;
    asm volatile("cp.async.wait_group 1;" ::: "memory");   // image landed
    __syncthreads();

    // ---- phase 1: conv1 + relu + pool (f32x2 FMA) -> fp16 s_a rows ----
    for (int m = tid; m < 364; m += 256) {
        const int r  = m / 26;
        const int pw = m % 26;
        float in[4][4];
#pragma unroll
        for (int rr = 0; rr < 4; rr++)
#pragma unroll
            for (int c = 0; c < 4; c++)
                in[rr][c] = s_img[(2 * r + rr) * 54 + 2 * pw + c];
        uint64_t ap[4][3];
#pragma unroll
        for (int rr = 0; rr < 4; rr++)
#pragma unroll
            for (int j = 0; j < 3; j++)
                ap[rr][j] = pack2(in[rr][j], in[rr][j + 1]);

        char* arow = (char*)s_a + m * 64;
        const int sw2 = (m >> 1) & 3;
#pragma unroll 2
        for (int oc2 = 0; oc2 < 16; oc2++) {
            const int oca = oc2 * 2, ocb = oca + 1;
            uint64_t va0 = 0ull, va1 = 0ull, vb0 = 0ull, vb1 = 0ull;
#pragma unroll
            for (int t = 0; t < 9; t++) {
                const uint64_t wa = s_w1d[oca * 9 + t];
                const uint64_t wb = s_w1d[ocb * 9 + t];
                fma2(va0, ap[t / 3][t % 3], wa);
                fma2(va1, ap[t / 3 + 1][t % 3], wa);
                fma2(vb0, ap[t / 3][t % 3], wb);
                fma2(vb1, ap[t / 3 + 1][t % 3], wb);
            }
            float a00, a01, a10, a11, b00, b01, b10, b11;
            unpack2(va0, a00, a01); unpack2(va1, a10, a11);
            unpack2(vb0, b00, b01); unpack2(vb1, b10, b11);
            float ma = fmaxf(fmaxf(a00, a01), fmaxf(a10, a11)) + s_b1[oca];
            float mb = fmaxf(fmaxf(b00, b01), fmaxf(b10, b11)) + s_b1[ocb];
            ma = fmaxf(ma, 0.0f);
            mb = fmaxf(mb, 0.0f);
            *(uint32_t*)(arow +
                ((((oca >> 3) ^ sw2) << 4) | ((oca & 7) << 1))) =
                cvt_f16x2(mb, ma);
        }
    }
    asm volatile("cp.async.wait_group 0;" ::: "memory");   // weights landed
    __syncthreads();

    // ---- conv2 mainloop: warp = 3 m16-tiles x 8 n8-tiles ----
    float acc[3][8][4];
#pragma unroll
    for (int i = 0; i < 3; i++)
#pragma unroll
        for (int n = 0; n < 8; n++)
#pragma unroll
            for (int q = 0; q < 4; q++) acc[i][n][q] = 0.0f;

    const int mbase = wid * 48;

    const uint32_t a_base = smem_u32(s_a);
    const uint32_t b_base = smem_u32(s_b);
    const int lrow15 = lane & 15;
    const int lhi    = lane >> 4;
    const int bq     = (lane >> 3) & 1;
    const int bsw    = ((lane & 7) >> 1) & 3;
    const int brow_l = ((lane >> 4) & 1) * 8 + (lane & 7);

#pragma unroll 1
    for (int s = 0; s < 9; s++) {
        const int roff = (s / 3) * 26 + (s % 3);
        const int arow = mbase + roff + lrow15;
        const int asw  = (arow >> 1) & 3;
        const uint32_t a_row_addr = a_base + arow * 64;
        const uint32_t b_s_base   = b_base + (s * 64 + brow_l) * 64;

#pragma unroll
        for (int ks = 0; ks < 2; ks++) {
            const uint32_t aaddr =
                a_row_addr + ((uint32_t)((((ks << 1) + lhi) ^ asw)) << 4);
            const uint32_t bchunk =
                ((uint32_t)((((ks << 1) + bq) ^ bsw)) << 4);

            uint32_t bf[4][4];
#pragma unroll
            for (int p = 0; p < 4; p++)
                ldmx4(bf[p], b_s_base + p * 1024 + bchunk);

#pragma unroll
            for (int i = 0; i < 3; i++) {
                uint32_t a[4];
                ldmx4(a, aaddr + i * 1024);
#pragma unroll
                for (int nt = 0; nt < 8; nt++)
                    mma_f16(acc[i][nt], a[0], a[1], a[2], a[3],
                            bf[nt >> 1][(nt & 1) * 2],
                            bf[nt >> 1][(nt & 1) * 2 + 1]);
            }
        }
    }
    __syncthreads();

    // ---- epilogue: bias + cvt -> fp16 [pix][66] smem ----
#pragma unroll
    for (int i = 0; i < 3; i++) {
        const int m0 = mbase + i * 16 + g;
        const int m1 = m0 + 8;
        const int r0 = m0 / 26, c0p = m0 % 26;
        const int r1 = m1 / 26, c1p = m1 % 26;
#pragma unroll
        for (int nt = 0; nt < 8; nt++) {
            const int col = nt * 8 + tig * 2;
            if (r0 < 12 && c0p < 24) {
                const int pix = r0 * 24 + c0p;
                *(uint32_t*)(s_epi + pix * 66 + col) =
                    cvt_f16x2(acc[i][nt][1] + s_bias[col + 1],
                              acc[i][nt][0] + s_bias[col]);
            }
            if (r1 < 12 && c1p < 24) {
                const int pix = r1 * 24 + c1p;
                *(uint32_t*)(s_epi + pix * 66 + col) =
                    cvt_f16x2(acc[i][nt][3] + s_bias[col + 1],
                              acc[i][nt][2] + s_bias[col]);
            }
        }
    }
    __syncthreads();

    // ---- 2x2 maxpool + relu (half2) -> fp16 NCHW flat (coalesced) ----
    __half* outp = g_pool2h + b * 9216 + half * 72;
    const __half2 z2 = __float2half2_rn(0.0f);
    for (int j = tid; j < 32 * 72; j += 256) {
        const int ocp = j / 72;
        const int p   = j % 72;
        const int pr  = p / 12, pw = p % 12;
        const __half* e = s_epi + ((2 * pr) * 24 + 2 * pw) * 66 + ocp * 2;
        const __half2 v00 = *(const __half2*)(e);
        const __half2 v01 = *(const __half2*)(e + 66);
        const __half2 v10 = *(const __half2*)(e + 24 * 66);
        const __half2 v11 = *(const __half2*)(e + 25 * 66);
        const __half2 mx =
            __hmax2(__hmax2(__hmax2(v00, v01), __hmax2(v10, v11)), z2);
        outp[(ocp * 2) * 144 + p]     = __low2half(mx);
        outp[(ocp * 2 + 1) * 144 + p] = __high2half(mx);
    }
}

// ============================================================================
// K2: fc1 split-K (16 ways) via fp16 m16n8k16 + cp.async 2-stage pipeline.
// Epilogue: red.global.add.f32 into g_fc1out.
// ============================================================================
__global__ void __launch_bounds__(256) fc1_tc()
{
    __shared__ __half sA[2][32 * 32];
    __shared__ __half sB[2][128 * 32];

    const int mt   = blockIdx.x;    // 0..15
    const int ks   = blockIdx.y;    // 0..15
    const int tid  = threadIdx.x;
    const int wid  = tid >> 5;
    const int lane = tid & 31;
    const int m0   = mt * 32;
    const int k0   = ks * 576;
    const int mi   = wid & 1;
    const int nq   = wid >> 1;      // 0..3

    uint32_t sa_off = 0;
    const __half* agp = nullptr;
    if (tid < 128) {
        const int m = tid >> 2, c = tid & 3;
        sa_off = m * 64 + ((c ^ ((m >> 1) & 3)) << 4);
        agp = g_pool2h + (m0 + m) * 9216 + k0 + c * 8;
    }
    uint32_t sb_off[2];
    const __half* bgp[2];
#pragma unroll
    for (int j = 0; j < 2; j++) {
        const int i = tid + j * 256;
        const int n = i >> 2, c = i & 3;
        sb_off[j] = n * 64 + ((c ^ ((n >> 1) & 3)) << 4);
        bgp[j] = g_fc1w_h + n * 9216 + k0 + c * 8;
    }

    const int lrow15 = lane & 15;
    const int lhi    = lane >> 4;
    const int bq     = (lane >> 3) & 1;
    const int bsw    = ((lane & 7) >> 1) & 3;
    const int brow_l = ((lane >> 4) & 1) * 8 + (lane & 7);

    const int arow = mi * 16 + lrow15;
    const int asw  = (arow >> 1) & 3;
    uint32_t aaddr_base[2], baddr_base[2];
#pragma unroll
    for (int buf = 0; buf < 2; buf++) {
        aaddr_base[buf] = smem_u32(sA[buf]) + arow * 64;
        baddr_base[buf] = smem_u32(sB[buf]) + (nq * 32 + brow_l) * 64;
    }

    float acc[4][4];
#pragma unroll
    for (int n = 0; n < 4; n++)
#pragma unroll
        for (int q = 0; q < 4; q++) acc[n][q] = 0.0f;

    auto issue = [&](int c, int buf) {
        const int koff = c * 32;
        if (tid < 128) cp16(smem_u32(sA[buf]) + sa_off, agp + koff);
        cp16(smem_u32(sB[buf]) + sb_off[0], bgp[0] + koff);
        cp16(smem_u32(sB[buf]) + sb_off[1], bgp[1] + koff);
        asm volatile("cp.async.commit_group;" ::: "memory");
    };

    issue(0, 0);

#pragma unroll 1
    for (int c = 0; c < 18; c++) {
        const int buf = c & 1;
        if (c + 1 < 18) {
            issue(c + 1, buf ^ 1);
            asm volatile("cp.async.wait_group 1;" ::: "memory");
        } else {
            asm volatile("cp.async.wait_group 0;" ::: "memory");
        }
        __syncthreads();

#pragma unroll
        for (int kstep = 0; kstep < 2; kstep++) {
            uint32_t a[4];
            ldmx4(a, aaddr_base[buf] +
                     ((uint32_t)((((kstep << 1) + lhi) ^ asw)) << 4));
            const uint32_t bchunk =
                ((uint32_t)((((kstep << 1) + bq) ^ bsw)) << 4);
            uint32_t bf[2][4];
#pragma unroll
            for (int p = 0; p < 2; p++)
                ldmx4(bf[p], baddr_base[buf] + p * 1024 + bchunk);
#pragma unroll
            for (int nt = 0; nt < 4; nt++)
                mma_f16(acc[nt], a[0], a[1], a[2], a[3],
                        bf[nt >> 1][(nt & 1) * 2],
                        bf[nt >> 1][(nt & 1) * 2 + 1]);
        }
        __syncthreads();
    }

    float* P = g_fc1out + m0 * 128;
    const int g   = lane >> 2;
    const int tig = lane & 3;
    const int r0  = mi * 16 + g;
#pragma unroll
    for (int n = 0; n < 4; n++) {
        const int c0 = nq * 32 + n * 8 + tig * 2;
        redg_add(P + r0 * 128 + c0,           acc[n][0]);
        redg_add(P + r0 * 128 + c0 + 1,       acc[n][1]);
        redg_add(P + (r0 + 8) * 128 + c0,     acc[n][2]);
        redg_add(P + (r0 + 8) * 128 + c0 + 1, acc[n][3]);
    }
}

// ============================================================================
// K3: bias + relu + fc2, warp-per-image.  grid 64 x 256 thr (8 warps/block).
// Lane: float4 slice of h; per output: 4-FMA partial + 5-stage shfl reduce.
// ============================================================================
__global__ void __launch_bounds__(256) fc_tail(
    const float* __restrict__ b1,
    const float* __restrict__ w2,
    const float* __restrict__ b2,
    float* __restrict__ out)
{
    const int wid  = threadIdx.x >> 5;
    const int lane = threadIdx.x & 31;
    const int b    = blockIdx.x * 8 + wid;

    const float4 hv = *(const float4*)(g_fc1out + b * 128 + lane * 4);
    const float4 bv = *(const float4*)(b1 + lane * 4);
    float4 h;
    h.x = fmaxf(hv.x + bv.x, 0.0f);
    h.y = fmaxf(hv.y + bv.y, 0.0f);
    h.z = fmaxf(hv.z + bv.z, 0.0f);
    h.w = fmaxf(hv.w + bv.w, 0.0f);

#pragma unroll
    for (int o = 0; o < 10; o++) {
        const float4 w4 = *(const float4*)(w2 + o * 128 + lane * 4);
        float p = h.x * w4.x;
        p = fmaf(h.y, w4.y, p);
        p = fmaf(h.z, w4.z, p);
        p = fmaf(h.w, w4.w, p);
#pragma unroll
        for (int s = 16; s > 0; s >>= 1)
            p += __shfl_xor_sync(0xffffffffu, p, s);
        if (lane == 0)
            out[b * 10 + o] = p + b2[o];
    }
}

// ============================================================================
extern "C" void kernel_launch(void* const* d_in, const int* in_sizes, int n_in,
                              void* d_out, int out_size)
{
    const float* x   = (const float*)d_in[0];
    const float* c1w = (const float*)d_in[1];
    const float* c1b = (const float*)d_in[2];
    const float* c2w = (const float*)d_in[3];
    const float* c2b = (const float*)d_in[4];
    const float* f1w = (const float*)d_in[5];
    const float* f1b = (const float*)d_in[6];
    const float* f2w = (const float*)d_in[7];
    const float* f2b = (const float*)d_in[8];
    float* out       = (float*)d_out;

    const int smem = 24576 + 36864 + 6480;   // 67920 B
    cudaFuncSetAttribute(convs_fused,
                         cudaFuncAttributeMaxDynamicSharedMemorySize, smem);

    cvt_weights<<<1188, 512>>>(f1w, c2w);
    convs_fused<<<1024, 256, smem>>>(x, c1w, c1b, c2b);

    dim3 g2(16, 16);
    fc1_tc<<<g2, 256>>>();

    fc_tail<<<64, 256>>>(f1b, f2w, f2b, out);
}

// round 17
// speedup vs baseline: 1.0675x; 1.0151x over previous
#include <cuda_runtime.h>
#include <cuda_fp16.h>
#include <cstdint>

// ---------------- scratch (device globals: allocation-free) ----------------
__device__ __half g_pool2h[512 * 9216];         // conv2 out, NCHW flat, fp16
__device__ __half g_fc1w_h[128 * 9216];         // fc1 weights, fp16
__device__ uint4  g_w2h[2304];                  // conv2 weights, pre-swizzled smem image
__device__ float  g_fc1out[512 * 128];          // fc1 accumulator (REDG target)

__device__ __forceinline__ uint32_t smem_u32(const void* p) {
    return (uint32_t)__cvta_generic_to_shared(p);
}
__device__ __forceinline__ uint64_t pack2(float lo, float hi) {
    uint64_t r;
    asm("mov.b64 %0, {%1, %2};" : "=l"(r) : "f"(lo), "f"(hi));
    return r;
}
__device__ __forceinline__ void fma2(uint64_t& d, uint64_t a, uint64_t b) {
    asm("fma.rn.f32x2 %0, %1, %2, %0;" : "+l"(d) : "l"(a), "l"(b));
}
__device__ __forceinline__ void unpack2(uint64_t v, float& lo, float& hi) {
    uint32_t l, h;
    asm("mov.b64 {%0, %1}, %2;" : "=r"(l), "=r"(h) : "l"(v));
    lo = __uint_as_float(l);
    hi = __uint_as_float(h);
}
__device__ __forceinline__ uint32_t cvt_f16x2(float hi, float lo) {
    uint32_t r;
    asm("cvt.rn.f16x2.f32 %0, %1, %2;" : "=r"(r) : "f"(hi), "f"(lo));
    return r;
}
__device__ __forceinline__ void cp16(uint32_t dst, const void* src) {
    asm volatile("cp.async.cg.shared.global [%0], [%1], 16;"
                 :: "r"(dst), "l"(src) : "memory");
}
__device__ __forceinline__ void redg_add(float* p, float v) {
    asm volatile("red.global.add.f32 [%0], %1;" :: "l"(p), "f"(v) : "memory");
}

// fp16 tensor-core MMA, fp32 accum (baseline PTX, sm_80+).
__device__ __forceinline__ void mma_f16(float c[4],
                                        uint32_t a0, uint32_t a1,
                                        uint32_t a2, uint32_t a3,
                                        uint32_t b0, uint32_t b1) {
    asm volatile(
        "mma.sync.aligned.m16n8k16.row.col.f32.f16.f16.f32 "
        "{%0,%1,%2,%3}, {%4,%5,%6,%7}, {%8,%9}, {%0,%1,%2,%3};"
        : "+f"(c[0]), "+f"(c[1]), "+f"(c[2]), "+f"(c[3])
        : "r"(a0), "r"(a1), "r"(a2), "r"(a3), "r"(b0), "r"(b1));
}
__device__ __forceinline__ void ldmx4(uint32_t r[4], uint32_t addr) {
    asm volatile(
        "ldmatrix.sync.aligned.m8n8.x4.shared.b16 {%0,%1,%2,%3}, [%4];"
        : "=r"(r[0]), "=r"(r[1]), "=r"(r[2]), "=r"(r[3]) : "r"(addr));
}

// ============================================================================
// K0: zero the fc1 REDG accumulator + conv2 weight pre-swizzle.
// (fc1 weight conversion moved into convs_fused phase 0.)
// ============================================================================
__global__ void __launch_bounds__(512) cvt_weights(const float* __restrict__ w2conv)
{
    const int bid = blockIdx.x;
    if (bid < 128) {
        g_fc1out[bid * 512 + threadIdx.x] = 0.0f;   // 128*512 = 65536 floats
    } else {
        const int i = (bid - 128) * 512 + threadIdx.x;   // 18432 total
        const int n = i / 288;
        const int r = i % 288;
        const int k = r / 9;
        const int s = r % 9;
        const int row = s * 64 + n;
        *(__half*)((char*)g_w2h + row * 64 +
            ((((k >> 3) ^ ((n >> 1) & 3)) << 4) | ((k & 7) << 1))) =
            __float2half_rn(w2conv[i]);
    }
}

// ============================================================================
// K1 (fused): conv1+relu+pool -> conv2 (fp16 m16n8k16) -> bias+relu+pool.
// Half-image CTAs, 2/SM, async staging. NEW: blocks 0-575 also convert the
// fc1 weights to fp16 (hidden in phase 0; stream order covers fc1_tc).
// conv1 patch loads now float2-based (8 LDS.64 vs 16 LDS.32 per pixel).
// ============================================================================
__global__ void __launch_bounds__(256, 2) convs_fused(
    const float* __restrict__ x,
    const float* __restrict__ w1,
    const float* __restrict__ b1,
    const float* __restrict__ b2,
    const float* __restrict__ w1fc)
{
    extern __shared__ char smc[];
    __half* s_a   = (__half*)smc;                 // 384 rows x 64B = 24576 B
    __half* s_b   = (__half*)(smc + 24576);       // 9*64 rows x 64B = 36864 B
    float*  s_img = (float*)(smc + 61440);        // 30*54 f32 = 6480 B
    __half* s_epi = (__half*)smc;                 // 288 pix x 66 (38016 B), reuse
    __shared__ uint64_t s_w1d[32 * 9];
    __shared__ float s_b1[32];
    __shared__ float s_bias[64];

    const int b    = blockIdx.x >> 1;
    const int half = blockIdx.x & 1;
    const int tid  = threadIdx.x;
    const int wid  = tid >> 5;
    const int lane = tid & 31;
    const int g    = lane >> 2;
    const int tig  = lane & 3;

    // ---- phase 0: async image (group 0) + async weights (group 1) ----
    {
        const char* src = (const char*)(x + b * 2916 + half * 24 * 54);
        const uint32_t dimg = smem_u32(s_img);
        for (int i = tid; i < 405; i += 256)          // 30x54 f32 = 405 x 16B
            cp16(dimg + i * 16, src + i * 16);
        asm volatile("cp.async.commit_group;" ::: "memory");

        const uint32_t dw = smem_u32(s_b);
#pragma unroll
        for (int j = 0; j < 9; j++)
            cp16(dw + (tid + j * 256) * 16, g_w2h + tid + j * 256);
        asm volatile("cp.async.commit_group;" ::: "memory");
    }
    // distributed fc1-weight conversion (blocks 0-575, 2048 elems each)
    if (blockIdx.x < 576) {
#pragma unroll
        for (int j = 0; j < 4; j++) {
            const int e = blockIdx.x * 1024 + j * 256 + tid;   // float2 index
            const float2 v = *(const float2*)(w1fc + e * 2);
            *(uint32_t*)(g_fc1w_h + e * 2) = cvt_f16x2(v.y, v.x);
        }
    }
    // small sync-path loads + A zero-pad while copies fly
    for (int i = tid; i < 32 * 9; i += 256) {
        const float wv = w1[i];
        s_w1d[i] = pack2(wv, wv);
    }
    if (tid < 32) s_b1[tid] = b1[tid];
    if (tid < 64) s_bias[tid] = b2[tid];
    for (int i = 364 * 16 + tid; i < 384 * 16; i += 256)
        ((uint32_t*)s_a)[i] = 0u;
    asm volatile("cp.async.wait_group 1;" ::: "memory");   // image landed
    __syncthreads();

    // ---- phase 1: conv1 + relu + pool (f32x2 FMA) -> fp16 s_a rows ----
    for (int m = tid; m < 364; m += 256) {
        const int r  = m / 26;
        const int pw = m % 26;
        uint64_t ap[4][3];
#pragma unroll
        for (int rr = 0; rr < 4; rr++) {
            const float2* rp = (const float2*)(s_img + (2 * r + rr) * 54 + 2 * pw);
            const float2 u = rp[0];
            const float2 v = rp[1];
            ap[rr][0] = pack2(u.x, u.y);
            ap[rr][1] = pack2(u.y, v.x);
            ap[rr][2] = pack2(v.x, v.y);
        }

        char* arow = (char*)s_a + m * 64;
        const int sw2 = (m >> 1) & 3;
#pragma unroll 2
        for (int oc2 = 0; oc2 < 16; oc2++) {
            const int oca = oc2 * 2, ocb = oca + 1;
            uint64_t va0 = 0ull, va1 = 0ull, vb0 = 0ull, vb1 = 0ull;
#pragma unroll
            for (int t = 0; t < 9; t++) {
                const uint64_t wa = s_w1d[oca * 9 + t];
                const uint64_t wb = s_w1d[ocb * 9 + t];
                fma2(va0, ap[t / 3][t % 3], wa);
                fma2(va1, ap[t / 3 + 1][t % 3], wa);
                fma2(vb0, ap[t / 3][t % 3], wb);
                fma2(vb1, ap[t / 3 + 1][t % 3], wb);
            }
            float a00, a01, a10, a11, b00, b01, b10, b11;
            unpack2(va0, a00, a01); unpack2(va1, a10, a11);
            unpack2(vb0, b00, b01); unpack2(vb1, b10, b11);
            float ma = fmaxf(fmaxf(a00, a01), fmaxf(a10, a11)) + s_b1[oca];
            float mb = fmaxf(fmaxf(b00, b01), fmaxf(b10, b11)) + s_b1[ocb];
            ma = fmaxf(ma, 0.0f);
            mb = fmaxf(mb, 0.0f);
            *(uint32_t*)(arow +
                ((((oca >> 3) ^ sw2) << 4) | ((oca & 7) << 1))) =
                cvt_f16x2(mb, ma);
        }
    }
    asm volatile("cp.async.wait_group 0;" ::: "memory");   // weights landed
    __syncthreads();

    // ---- conv2 mainloop: warp = 3 m16-tiles x 8 n8-tiles ----
    float acc[3][8][4];
#pragma unroll
    for (int i = 0; i < 3; i++)
#pragma unroll
        for (int n = 0; n < 8; n++)
#pragma unroll
            for (int q = 0; q < 4; q++) acc[i][n][q] = 0.0f;

    const int mbase = wid * 48;

    const uint32_t a_base = smem_u32(s_a);
    const uint32_t b_base = smem_u32(s_b);
    const int lrow15 = lane & 15;
    const int lhi    = lane >> 4;
    const int bq     = (lane >> 3) & 1;
    const int bsw    = ((lane & 7) >> 1) & 3;
    const int brow_l = ((lane >> 4) & 1) * 8 + (lane & 7);

#pragma unroll 1
    for (int s = 0; s < 9; s++) {
        const int roff = (s / 3) * 26 + (s % 3);
        const int arow = mbase + roff + lrow15;
        const int asw  = (arow >> 1) & 3;
        const uint32_t a_row_addr = a_base + arow * 64;
        const uint32_t b_s_base   = b_base + (s * 64 + brow_l) * 64;

#pragma unroll
        for (int ks = 0; ks < 2; ks++) {
            const uint32_t aaddr =
                a_row_addr + ((uint32_t)((((ks << 1) + lhi) ^ asw)) << 4);
            const uint32_t bchunk =
                ((uint32_t)((((ks << 1) + bq) ^ bsw)) << 4);

            uint32_t bf[4][4];
#pragma unroll
            for (int p = 0; p < 4; p++)
                ldmx4(bf[p], b_s_base + p * 1024 + bchunk);

#pragma unroll
            for (int i = 0; i < 3; i++) {
                uint32_t a[4];
                ldmx4(a, aaddr + i * 1024);
#pragma unroll
                for (int nt = 0; nt < 8; nt++)
                    mma_f16(acc[i][nt], a[0], a[1], a[2], a[3],
                            bf[nt >> 1][(nt & 1) * 2],
                            bf[nt >> 1][(nt & 1) * 2 + 1]);
            }
        }
    }
    __syncthreads();

    // ---- epilogue: bias + cvt -> fp16 [pix][66] smem ----
#pragma unroll
    for (int i = 0; i < 3; i++) {
        const int m0 = mbase + i * 16 + g;
        const int m1 = m0 + 8;
        const int r0 = m0 / 26, c0p = m0 % 26;
        const int r1 = m1 / 26, c1p = m1 % 26;
#pragma unroll
        for (int nt = 0; nt < 8; nt++) {
            const int col = nt * 8 + tig * 2;
            if (r0 < 12 && c0p < 24) {
                const int pix = r0 * 24 + c0p;
                *(uint32_t*)(s_epi + pix * 66 + col) =
                    cvt_f16x2(acc[i][nt][1] + s_bias[col + 1],
                              acc[i][nt][0] + s_bias[col]);
            }
            if (r1 < 12 && c1p < 24) {
                const int pix = r1 * 24 + c1p;
                *(uint32_t*)(s_epi + pix * 66 + col) =
                    cvt_f16x2(acc[i][nt][3] + s_bias[col + 1],
                              acc[i][nt][2] + s_bias[col]);
            }
        }
    }
    __syncthreads();

    // ---- 2x2 maxpool + relu (half2) -> fp16 NCHW flat (coalesced) ----
    __half* outp = g_pool2h + b * 9216 + half * 72;
    const __half2 z2 = __float2half2_rn(0.0f);
    for (int j = tid; j < 32 * 72; j += 256) {
        const int ocp = j / 72;
        const int p   = j % 72;
        const int pr  = p / 12, pw = p % 12;
        const __half* e = s_epi + ((2 * pr) * 24 + 2 * pw) * 66 + ocp * 2;
        const __half2 v00 = *(const __half2*)(e);
        const __half2 v01 = *(const __half2*)(e + 66);
        const __half2 v10 = *(const __half2*)(e + 24 * 66);
        const __half2 v11 = *(const __half2*)(e + 25 * 66);
        const __half2 mx =
            __hmax2(__hmax2(__hmax2(v00, v01), __hmax2(v10, v11)), z2);
        outp[(ocp * 2) * 144 + p]     = __low2half(mx);
        outp[(ocp * 2 + 1) * 144 + p] = __high2half(mx);
    }
}

// ============================================================================
// K2: fc1 split-K (16 ways) via fp16 m16n8k16 + cp.async 2-stage pipeline.
// Epilogue: red.global.add.f32 into g_fc1out.
// ============================================================================
__global__ void __launch_bounds__(256) fc1_tc()
{
    __shared__ __half sA[2][32 * 32];
    __shared__ __half sB[2][128 * 32];

    const int mt   = blockIdx.x;    // 0..15
    const int ks   = blockIdx.y;    // 0..15
    const int tid  = threadIdx.x;
    const int wid  = tid >> 5;
    const int lane = tid & 31;
    const int m0   = mt * 32;
    const int k0   = ks * 576;
    const int mi   = wid & 1;
    const int nq   = wid >> 1;      // 0..3

    uint32_t sa_off = 0;
    const __half* agp = nullptr;
    if (tid < 128) {
        const int m = tid >> 2, c = tid & 3;
        sa_off = m * 64 + ((c ^ ((m >> 1) & 3)) << 4);
        agp = g_pool2h + (m0 + m) * 9216 + k0 + c * 8;
    }
    uint32_t sb_off[2];
    const __half* bgp[2];
#pragma unroll
    for (int j = 0; j < 2; j++) {
        const int i = tid + j * 256;
        const int n = i >> 2, c = i & 3;
        sb_off[j] = n * 64 + ((c ^ ((n >> 1) & 3)) << 4);
        bgp[j] = g_fc1w_h + n * 9216 + k0 + c * 8;
    }

    const int lrow15 = lane & 15;
    const int lhi    = lane >> 4;
    const int bq     = (lane >> 3) & 1;
    const int bsw    = ((lane & 7) >> 1) & 3;
    const int brow_l = ((lane >> 4) & 1) * 8 + (lane & 7);

    const int arow = mi * 16 + lrow15;
    const int asw  = (arow >> 1) & 3;
    uint32_t aaddr_base[2], baddr_base[2];
#pragma unroll
    for (int buf = 0; buf < 2; buf++) {
        aaddr_base[buf] = smem_u32(sA[buf]) + arow * 64;
        baddr_base[buf] = smem_u32(sB[buf]) + (nq * 32 + brow_l) * 64;
    }

    float acc[4][4];
#pragma unroll
    for (int n = 0; n < 4; n++)
#pragma unroll
        for (int q = 0; q < 4; q++) acc[n][q] = 0.0f;

    auto issue = [&](int c, int buf) {
        const int koff = c * 32;
        if (tid < 128) cp16(smem_u32(sA[buf]) + sa_off, agp + koff);
        cp16(smem_u32(sB[buf]) + sb_off[0], bgp[0] + koff);
        cp16(smem_u32(sB[buf]) + sb_off[1], bgp[1] + koff);
        asm volatile("cp.async.commit_group;" ::: "memory");
    };

    issue(0, 0);

#pragma unroll 1
    for (int c = 0; c < 18; c++) {
        const int buf = c & 1;
        if (c + 1 < 18) {
            issue(c + 1, buf ^ 1);
            asm volatile("cp.async.wait_group 1;" ::: "memory");
        } else {
            asm volatile("cp.async.wait_group 0;" ::: "memory");
        }
        __syncthreads();

#pragma unroll
        for (int kstep = 0; kstep < 2; kstep++) {
            uint32_t a[4];
            ldmx4(a, aaddr_base[buf] +
                     ((uint32_t)((((kstep << 1) + lhi) ^ asw)) << 4));
            const uint32_t bchunk =
                ((uint32_t)((((kstep << 1) + bq) ^ bsw)) << 4);
            uint32_t bf[2][4];
#pragma unroll
            for (int p = 0; p < 2; p++)
                ldmx4(bf[p], baddr_base[buf] + p * 1024 + bchunk);
#pragma unroll
            for (int nt = 0; nt < 4; nt++)
                mma_f16(acc[nt], a[0], a[1], a[2], a[3],
                        bf[nt >> 1][(nt & 1) * 2],
                        bf[nt >> 1][(nt & 1) * 2 + 1]);
        }
        __syncthreads();
    }

    float* P = g_fc1out + m0 * 128;
    const int g   = lane >> 2;
    const int tig = lane & 3;
    const int r0  = mi * 16 + g;
#pragma unroll
    for (int n = 0; n < 4; n++) {
        const int c0 = nq * 32 + n * 8 + tig * 2;
        redg_add(P + r0 * 128 + c0,           acc[n][0]);
        redg_add(P + r0 * 128 + c0 + 1,       acc[n][1]);
        redg_add(P + (r0 + 8) * 128 + c0,     acc[n][2]);
        redg_add(P + (r0 + 8) * 128 + c0 + 1, acc[n][3]);
    }
}

// ============================================================================
// K3: bias + relu + fc2, warp-per-image.  grid 64 x 256 thr (8 warps/block).
// ============================================================================
__global__ void __launch_bounds__(256) fc_tail(
    const float* __restrict__ b1,
    const float* __restrict__ w2,
    const float* __restrict__ b2,
    float* __restrict__ out)
{
    const int wid  = threadIdx.x >> 5;
    const int lane = threadIdx.x & 31;
    const int b    = blockIdx.x * 8 + wid;

    const float4 hv = *(const float4*)(g_fc1out + b * 128 + lane * 4);
    const float4 bv = *(const float4*)(b1 + lane * 4);
    float4 h;
    h.x = fmaxf(hv.x + bv.x, 0.0f);
    h.y = fmaxf(hv.y + bv.y, 0.0f);
    h.z = fmaxf(hv.z + bv.z, 0.0f);
    h.w = fmaxf(hv.w + bv.w, 0.0f);

#pragma unroll
    for (int o = 0; o < 10; o++) {
        const float4 w4 = *(const float4*)(w2 + o * 128 + lane * 4);
        float p = h.x * w4.x;
        p = fmaf(h.y, w4.y, p);
        p = fmaf(h.z, w4.z, p);
        p = fmaf(h.w, w4.w, p);
#pragma unroll
        for (int s = 16; s > 0; s >>= 1)
            p += __shfl_xor_sync(0xffffffffu, p, s);
        if (lane == 0)
            out[b * 10 + o] = p + b2[o];
    }
}

// ============================================================================
extern "C" void kernel_launch(void* const* d_in, const int* in_sizes, int n_in,
                              void* d_out, int out_size)
{
    const float* x   = (const float*)d_in[0];
    const float* c1w = (const float*)d_in[1];
    const float* c1b = (const float*)d_in[2];
    const float* c2w = (const float*)d_in[3];
    const float* c2b = (const float*)d_in[4];
    const float* f1w = (const float*)d_in[5];
    const float* f1b = (const float*)d_in[6];
    const float* f2w = (const float*)d_in[7];
    const float* f2b = (const float*)d_in[8];
    float* out       = (float*)d_out;

    const int smem = 24576 + 36864 + 6480;   // 67920 B
    cudaFuncSetAttribute(convs_fused,
                         cudaFuncAttributeMaxDynamicSharedMemorySize, smem);

    cvt_weights<<<164, 512>>>(c2w);
    convs_fused<<<1024, 256, smem>>>(x, c1w, c1b, c2b, f1w);

    dim3 g2(16, 16);
    fc1_tc<<<g2, 256>>>();

    fc_tail<<<64, 256>>>(f1b, f2w, f2b, out);
}